// round 7
// baseline (speedup 1.0000x reference)
#include <cuda_runtime.h>
#include <math.h>

typedef unsigned long long ull;

#define NBC    6          // B*C
#define NLEV   6
#define NSTAT  9          // S1 S2 S3 S4 S5 Sm1 Sm2 T2(x*log2 x) count
#define GXA    256        // l0 grid.x per bc -> 262144/(256*256)=4 exact iters
#define NTILB  64         // pyr2 tiles per bc (4x4x4 of 16^3 L1-cell cubes)

// Static __device__ scratch (allocation-free).
__device__ float        g_l1[NBC * 64 * 64 * 64];      // level-1 map (64^3 per bc)
__device__ double       g_partA[NBC][GXA][18];         // L0(9)+L1(9) per l0-block
__device__ double       g_partB[NBC][NTILB][54];       // L0L1 fold(18) + L2..L5 (36)
__device__ unsigned int g_ctr;                         // last-block counter (reset by l0)

// ---- packed f32x2 helpers (Blackwell 2xFP32; ptxas won't auto-emit) ----
__device__ __forceinline__ ull pk2(float lo, float hi) {
    ull r; asm("mov.b64 %0, {%1, %2};" : "=l"(r) : "f"(lo), "f"(hi)); return r;
}
__device__ __forceinline__ float2 upk2(ull v) {
    float2 f; asm("mov.b64 {%0, %1}, %2;" : "=f"(f.x), "=f"(f.y) : "l"(v)); return f;
}
__device__ __forceinline__ ull add2(ull a, ull b) {
    ull r; asm("add.rn.f32x2 %0, %1, %2;" : "=l"(r) : "l"(a), "l"(b)); return r;
}
__device__ __forceinline__ ull mul2(ull a, ull b) {
    ull r; asm("mul.rn.f32x2 %0, %1, %2;" : "=l"(r) : "l"(a), "l"(b)); return r;
}
__device__ __forceinline__ ull fma2(ull a, ull b, ull c) {
    ull r; asm("fma.rn.f32x2 %0, %1, %2, %3;" : "=l"(r) : "l"(a), "l"(b), "l"(c)); return r;
}
__device__ __forceinline__ float rcpa(float x) {
    float r; asm("rcp.approx.f32 %0, %1;" : "=f"(r) : "f"(x)); return r;
}
__device__ __forceinline__ float lg2a(float x) {
    float r; asm("lg2.approx.f32 %0, %1;" : "=f"(r) : "f"(x)); return r;
}

// Packed stat accumulation for 2 nonzero values.
__device__ __forceinline__ void acc_pair(ull x, ull& S1, ull& S2, ull& S3, ull& S4,
                                         ull& S5, ull& Sm1, ull& Sm2, ull& T2) {
    float2 f = upk2(x);
    ull inv = pk2(rcpa(f.x), rcpa(f.y));    // 2x MUFU.RCP
    ull lg  = pk2(lg2a(f.x), lg2a(f.y));    // 2x MUFU.LG2
    S1 = add2(S1, x);
    ull xx = mul2(x, x);
    S2 = add2(S2, xx);
    ull x3 = mul2(xx, x);
    S3 = add2(S3, x3);
    S4 = fma2(xx, xx, S4);
    S5 = fma2(x3, xx, S5);
    Sm1 = add2(Sm1, inv);
    Sm2 = fma2(inv, inv, Sm2);
    T2  = fma2(x, lg, T2);
}

// Scalar zero-skipping accumulation into packed accumulators (lo lane).
__device__ __forceinline__ void acc_one(float v, ull& S1, ull& S2, ull& S3, ull& S4,
                                        ull& S5, ull& Sm1, ull& Sm2, ull& T2, float& cnt) {
    if (v != 0.0f) {
        float inv = rcpa(v), lg = lg2a(v);
        float v2 = v * v, v3 = v2 * v;
        S1 = add2(S1, pk2(v, 0.f));
        S2 = add2(S2, pk2(v2, 0.f));
        S3 = add2(S3, pk2(v3, 0.f));
        S4 = add2(S4, pk2(v2 * v2, 0.f));
        S5 = add2(S5, pk2(v3 * v2, 0.f));
        Sm1 = add2(Sm1, pk2(inv, 0.f));
        Sm2 = add2(Sm2, pk2(inv * inv, 0.f));
        T2 = add2(T2, pk2(v * lg, 0.f));
        cnt += 1.0f;
    }
}

// Scalar zero-skipping accumulation into a 9-float array.
__device__ __forceinline__ void acc_scalar(float v, float* st) {
    if (v != 0.0f) {
        float inv = rcpa(v), lg = lg2a(v);
        float v2 = v * v, v3 = v2 * v;
        st[0] += v;  st[1] += v2;  st[2] += v3;
        st[3] += v2 * v2;  st[4] += v3 * v2;
        st[5] += inv;  st[6] += inv * inv;
        st[7] += v * lg;  st[8] += 1.0f;
    }
}

__device__ __forceinline__ float wred32(float v) {
#pragma unroll
    for (int o = 16; o; o >>= 1) v += __shfl_down_sync(0xFFFFFFFFu, v, o);
    return v;
}

// Process one 2x2x2 octant given its 4 packed float2 loads. Returns pooled sum.
__device__ __forceinline__ float do_octant(ull q0, ull q1, ull q2, ull q3,
                                           ull& S1, ull& S2, ull& S3, ull& S4,
                                           ull& S5, ull& Sm1, ull& Sm2, ull& T2,
                                           float& cnt) {
    ull ps = add2(add2(q0, q1), add2(q2, q3));
    float2 pf = upk2(ps);
    float psum = pf.x + pf.y;
    // zero test: product of all 8 (underflow -> safe fallback to slow path)
    ull pr = mul2(mul2(q0, q1), mul2(q2, q3));
    float2 prf = upk2(pr);
    if (prf.x * prf.y != 0.0f) {
        acc_pair(q0, S1, S2, S3, S4, S5, Sm1, Sm2, T2);
        acc_pair(q1, S1, S2, S3, S4, S5, Sm1, Sm2, T2);
        acc_pair(q2, S1, S2, S3, S4, S5, Sm1, Sm2, T2);
        acc_pair(q3, S1, S2, S3, S4, S5, Sm1, Sm2, T2);
        cnt += 8.0f;
    } else {
        float2 a = upk2(q0), b = upk2(q1), c = upk2(q2), d = upk2(q3);
        float vals[8] = {a.x, a.y, b.x, b.y, c.x, c.y, d.x, d.y};
#pragma unroll
        for (int j = 0; j < 8; j++)
            acc_one(vals[j], S1, S2, S3, S4, S5, Sm1, Sm2, T2, cnt);
    }
    return psum;
}

// -------- Kernel A: level-0 + level-1 stats, write L1 map. grid (GXA,6), 256 thr. --------
__global__ void __launch_bounds__(256) l0_kernel(const float* __restrict__ img) {
    if ((blockIdx.x | blockIdx.y | threadIdx.x) == 0) g_ctr = 0;   // reset for pyr2

    const int bc = blockIdx.y;
    const float* __restrict__ inp = img + ((size_t)bc << 21);
    float* __restrict__ outp = g_l1 + ((size_t)bc << 18);

    ull S1 = 0, S2 = 0, S3 = 0, S4 = 0, S5 = 0, Sm1 = 0, Sm2 = 0, T2 = 0;
    float cnt0 = 0.0f;
    float st1[9];
#pragma unroll
    for (int j = 0; j < 9; j++) st1[j] = 0.0f;

    const int stride = GXA * 256;                        // 65536
    const int idx0 = blockIdx.x * 256 + threadIdx.x;

#pragma unroll
    for (int g = 0; g < 2; g++) {                        // 2 groups x 2 iterations
        ull v[8];
        int idxs[2];
#pragma unroll
        for (int it = 0; it < 2; it++) {                 // front-batch 8 loads (MLP=8)
            int idx = idx0 + (g * 2 + it) * stride;
            idxs[it] = idx;
            int ow = idx & 63, oh = (idx >> 6) & 63, od = idx >> 12;
            int base = (od << 15) + (oh << 8) + (ow << 1);
            v[it * 4 + 0] = *reinterpret_cast<const ull*>(inp + base);
            v[it * 4 + 1] = *reinterpret_cast<const ull*>(inp + base + 128);
            v[it * 4 + 2] = *reinterpret_cast<const ull*>(inp + base + 16384);
            v[it * 4 + 3] = *reinterpret_cast<const ull*>(inp + base + 16512);
        }
#pragma unroll
        for (int it = 0; it < 2; it++) {
            float psum = do_octant(v[it * 4], v[it * 4 + 1], v[it * 4 + 2], v[it * 4 + 3],
                                   S1, S2, S3, S4, S5, Sm1, Sm2, T2, cnt0);
            acc_scalar(psum, st1);                       // level-1 stats inline
            outp[idxs[it]] = psum;
        }
    }

    // block reduce 18 stats -> g_partA[bc][blockIdx.x]
    float st0[9];
    {
        float2 f;
        f = upk2(S1);  st0[0] = f.x + f.y;
        f = upk2(S2);  st0[1] = f.x + f.y;
        f = upk2(S3);  st0[2] = f.x + f.y;
        f = upk2(S4);  st0[3] = f.x + f.y;
        f = upk2(S5);  st0[4] = f.x + f.y;
        f = upk2(Sm1); st0[5] = f.x + f.y;
        f = upk2(Sm2); st0[6] = f.x + f.y;
        f = upk2(T2);  st0[7] = f.x + f.y;
        st0[8] = cnt0;
    }
    __shared__ double sm[8][18];
    int lane = threadIdx.x & 31, warp = threadIdx.x >> 5;
#pragma unroll
    for (int j = 0; j < 9; j++) {
        float a0 = wred32(st0[j]);
        float a1 = wred32(st1[j]);
        if (lane == 0) { sm[warp][j] = (double)a0; sm[warp][9 + j] = (double)a1; }
    }
    __syncthreads();
    if (threadIdx.x < 18) {
        double s = 0.0;
#pragma unroll
        for (int w = 0; w < 8; w++) s += sm[w][threadIdx.x];
        g_partA[bc][blockIdx.x][threadIdx.x] = s;
    }
}

// -------- Kernel B: levels 2..5 + partA fold + last-block finalize. --------
// grid (64, 6), 256 threads. Block owns 16^3 L1 cells; thread computes 2 L2 cells.
__global__ void __launch_bounds__(256) pyr2_kernel(const int* __restrict__ bounds,
                                                   float* __restrict__ out) {
    const int tile = blockIdx.x;                  // 0..63
    const int bc   = blockIdx.y;
    const int tid  = threadIdx.x;

    __shared__ float  l2s[512];
    __shared__ float  l3s[64];
    __shared__ double sacc[54];

    // exclusive fold of this block's 4 partA rows (L0+L1, 18 stats)
    if (tid >= 32 && tid < 50) {
        int j = tid - 32;
        double s = 0.0;
#pragma unroll
        for (int r = 0; r < 4; r++) s += g_partA[bc][(tile << 2) + r][j];
        sacc[j] = s;
    }
    if (tid < 32 && tid >= 18) { }                // (sacc[18..53] zeroed below)
    if (tid < 18) { }                             // keep lanes free
    if (tid >= 50 && tid < 86) sacc[tid - 50 + 18] = 0.0;   // zero sacc[18..53]

    const int tw = tile & 3, th = (tile >> 2) & 3, td = tile >> 4;
    const int pw = tid & 3, ph = (tid >> 2) & 7, pd = tid >> 5;
    const int w1 = tw * 16 + pw * 4;
    const int h1 = th * 16 + ph * 2;
    const int d1 = td * 16 + pd * 2;

    const float* __restrict__ p = g_l1 + ((size_t)bc << 18) + (d1 << 12) + (h1 << 6) + w1;

    // 8 packed loads: rows (d,h) x {+0,+2}
    ull q00a = *reinterpret_cast<const ull*>(p);
    ull q00b = *reinterpret_cast<const ull*>(p + 2);
    ull q01a = *reinterpret_cast<const ull*>(p + 64);
    ull q01b = *reinterpret_cast<const ull*>(p + 66);
    ull q10a = *reinterpret_cast<const ull*>(p + 4096);
    ull q10b = *reinterpret_cast<const ull*>(p + 4098);
    ull q11a = *reinterpret_cast<const ull*>(p + 4160);
    ull q11b = *reinterpret_cast<const ull*>(p + 4162);

    float2 fa = upk2(add2(add2(q00a, q01a), add2(q10a, q11a)));
    float2 fb = upk2(add2(add2(q00b, q01b), add2(q10b, q11b)));
    float l2a = fa.x + fa.y;
    float l2b = fb.x + fb.y;

    float st2[9];
#pragma unroll
    for (int j = 0; j < 9; j++) st2[j] = 0.0f;
    acc_scalar(l2a, st2);
    acc_scalar(l2b, st2);

    int l2i = (pd << 6) + (ph << 3) + (pw << 1);
    l2s[l2i] = l2a;
    l2s[l2i + 1] = l2b;
    __syncthreads();

    // L3: 64 threads pool 2x2x2 from l2s (8x8x8 layout)
    float st3[9];
    if (tid < 64) {
#pragma unroll
        for (int j = 0; j < 9; j++) st3[j] = 0.0f;
        int jw = tid & 3, jh = (tid >> 2) & 3, jd = tid >> 4;
        int b3 = (jd << 7) + (jh << 4) + (jw << 1);
        float l3v = 0.0f;
#pragma unroll
        for (int di = 0; di < 2; di++)
#pragma unroll
            for (int hi = 0; hi < 2; hi++)
#pragma unroll
                for (int wi = 0; wi < 2; wi++)
                    l3v += l2s[b3 + (di << 6) + (hi << 3) + wi];
        acc_scalar(l3v, st3);
        l3s[tid] = l3v;
    }
    __syncthreads();

    // L4: 8 threads pool from l3s (4x4x4); L5: block total via shfl in warp 0
    if (tid < 8) {
        int mw = tid & 1, mh = (tid >> 1) & 1, md = tid >> 2;
        int b4 = (md << 5) + (mh << 3) + (mw << 1);
        float l4v = 0.0f;
#pragma unroll
        for (int di = 0; di < 2; di++)
#pragma unroll
            for (int hi = 0; hi < 2; hi++)
#pragma unroll
                for (int wi = 0; wi < 2; wi++)
                    l4v += l3s[b4 + (di << 4) + (hi << 2) + wi];
        float st4[9];
#pragma unroll
        for (int j = 0; j < 9; j++) st4[j] = 0.0f;
        acc_scalar(l4v, st4);
        float l5v = l4v;
#pragma unroll
        for (int o = 4; o; o >>= 1) {
            l5v += __shfl_down_sync(0xFFu, l5v, o);
#pragma unroll
            for (int j = 0; j < 9; j++) st4[j] += __shfl_down_sync(0xFFu, st4[j], o);
        }
        if (tid == 0) {
#pragma unroll
            for (int j = 0; j < 9; j++) sacc[36 + j] = (double)st4[j];   // L4
            float st5[9];
#pragma unroll
            for (int j = 0; j < 9; j++) st5[j] = 0.0f;
            acc_scalar(l5v, st5);
#pragma unroll
            for (int j = 0; j < 9; j++) sacc[45 + j] = (double)st5[j];   // L5
        }
    }

    // reduce st2 (256 thr) and st3 (64 thr) into sacc
    {
        int lane = tid & 31;
#pragma unroll
        for (int j = 0; j < 9; j++) {
            float a2 = wred32(st2[j]);
            if (lane == 0) atomicAdd(&sacc[18 + j], (double)a2);
        }
        if (tid < 64) {
#pragma unroll
            for (int j = 0; j < 9; j++) {
                float a3 = wred32(st3[j]);
                if (lane == 0) atomicAdd(&sacc[27 + j], (double)a3);
            }
        }
    }
    __syncthreads();

    if (tid < 54) g_partB[bc][tile][tid] = sacc[tid];

    // ---------- last-block finalize ----------
    __threadfence();
    __shared__ unsigned int isLast;
    if (tid == 0) isLast = (atomicAdd(&g_ctr, 1) == NTILB * NBC - 1) ? 1u : 0u;
    __syncthreads();
    if (!isLast) return;
    __threadfence();

    __shared__ float acc[NBC][NLEV][NSTAT];
    for (int u = tid; u < NBC * 54; u += 256) {
        int abc = u / 54, j = u % 54;
        double s = 0.0;
#pragma unroll 8
        for (int t = 0; t < NTILB; t++) s += g_partB[abc][t][j];
        int level, stat;
        if (j < 18) { level = j / 9; stat = j % 9; }
        else        { level = 2 + (j - 18) / 9; stat = (j - 18) % 9; }
        acc[abc][level][stat] = (float)s;
    }
    __syncthreads();

    if (tid >= NBC * 8) return;
    int obc = tid >> 3;
    int k   = bounds[tid & 7];

    const float LN2 = 0.69314718055994531f;
    float b   = acc[obc][0][0];
    float lnb = logf(b);

    float sp = 0.0f, spq = 0.0f;
    for (int s = 0; s < NLEV; s++) {
        const float* a = acc[obc][s];
        float pv;
        if (k == 1) {
            pv = (a[7] * LN2) / b - lnb;
        } else if (k == 0) {
            pv = logf(a[8]);
        } else {
            float S;
            switch (k) {
                case  2: S = a[1]; break;
                case  3: S = a[2]; break;
                case  4: S = a[3]; break;
                case  5: S = a[4]; break;
                case -1: S = a[5]; break;
                case -2: S = a[6]; break;
                default: S = __int_as_float(0x7FC00000); break;
            }
            pv = logf(S) - (float)k * lnb;
        }
        sp  += pv;
        spq += pv * ((float)s * LN2);
    }
    const float qs  = 15.0f * LN2;
    const float q2s = 55.0f * LN2 * LN2;
    const float den = 6.0f * q2s - qs * qs;
    float aa = (k == 1) ? 1.0f : 1.0f / (float)(k - 1);
    out[tid] = aa * (6.0f * spq - sp * qs) / den;
}

extern "C" void kernel_launch(void* const* d_in, const int* in_sizes, int n_in,
                              void* d_out, int out_size) {
    const float* img    = (const float*)d_in[0];
    const int*   bounds = (const int*)d_in[1];
    float*       out    = (float*)d_out;

    l0_kernel<<<dim3(GXA, NBC), 256>>>(img);               // L0+L1 stats + L1 map
    pyr2_kernel<<<dim3(NTILB, NBC), 256>>>(bounds, out);   // L2..L5 + finalize
}

// round 11
// speedup vs baseline: 1.5768x; 1.5768x over previous
#include <cuda_runtime.h>
#include <math.h>

typedef unsigned long long ull;

#define NBC 6            // B*C
#define NB1 768          // phase-1 blocks (128 per bc); 768*256 threads = 196608 L2 cells
#define NB2 48           // phase-2 blocks (8 per bc)

// Static __device__ scratch (allocation-free).
__device__ float        g_l2map[NBC << 15];   // 32^3 L2 map per bc
__device__ double       g_part1[NB1][18];     // L0(9)+L1(9) per phase-1 block
__device__ double       g_part2[NB2][54];     // [0..17]=pre-reduced L0L1, [18..53]=L2..L5
__device__ unsigned int g_ctr1;               // phase-1 arrivals (reset by finalize)
__device__ unsigned int g_ctr2;               // phase-2 arrivals (reset by finalize)

// ---- packed f32x2 helpers (Blackwell 2xFP32; ptxas won't auto-emit) ----
__device__ __forceinline__ ull pk2(float lo, float hi) {
    ull r; asm("mov.b64 %0, {%1, %2};" : "=l"(r) : "f"(lo), "f"(hi)); return r;
}
__device__ __forceinline__ float2 upk2(ull v) {
    float2 f; asm("mov.b64 {%0, %1}, %2;" : "=f"(f.x), "=f"(f.y) : "l"(v)); return f;
}
__device__ __forceinline__ ull add2(ull a, ull b) {
    ull r; asm("add.rn.f32x2 %0, %1, %2;" : "=l"(r) : "l"(a), "l"(b)); return r;
}
__device__ __forceinline__ ull mul2(ull a, ull b) {
    ull r; asm("mul.rn.f32x2 %0, %1, %2;" : "=l"(r) : "l"(a), "l"(b)); return r;
}
__device__ __forceinline__ ull fma2(ull a, ull b, ull c) {
    ull r; asm("fma.rn.f32x2 %0, %1, %2, %3;" : "=l"(r) : "l"(a), "l"(b), "l"(c)); return r;
}
__device__ __forceinline__ float rcpa(float x) {
    float r; asm("rcp.approx.f32 %0, %1;" : "=f"(r) : "f"(x)); return r;
}
__device__ __forceinline__ float lg2a(float x) {
    float r; asm("lg2.approx.f32 %0, %1;" : "=f"(r) : "f"(x)); return r;
}

// Packed stat accumulation for 2 nonzero values.
__device__ __forceinline__ void acc_pair(ull x, ull& S1, ull& S2, ull& S3, ull& S4,
                                         ull& S5, ull& Sm1, ull& Sm2, ull& T2) {
    float2 f = upk2(x);
    ull inv = pk2(rcpa(f.x), rcpa(f.y));    // 2x MUFU.RCP
    ull lg  = pk2(lg2a(f.x), lg2a(f.y));    // 2x MUFU.LG2
    S1 = add2(S1, x);
    ull xx = mul2(x, x);
    S2 = add2(S2, xx);
    ull x3 = mul2(xx, x);
    S3 = add2(S3, x3);
    S4 = fma2(xx, xx, S4);
    S5 = fma2(x3, xx, S5);
    Sm1 = add2(Sm1, inv);
    Sm2 = fma2(inv, inv, Sm2);
    T2  = fma2(x, lg, T2);
}

// Scalar zero-skipping accumulation into packed accumulators (lo lane).
__device__ __forceinline__ void acc_one(float v, ull& S1, ull& S2, ull& S3, ull& S4,
                                        ull& S5, ull& Sm1, ull& Sm2, ull& T2, float& cnt) {
    if (v != 0.0f) {
        float inv = rcpa(v), lg = lg2a(v);
        float v2 = v * v, v3 = v2 * v;
        S1 = add2(S1, pk2(v, 0.f));
        S2 = add2(S2, pk2(v2, 0.f));
        S3 = add2(S3, pk2(v3, 0.f));
        S4 = add2(S4, pk2(v2 * v2, 0.f));
        S5 = add2(S5, pk2(v3 * v2, 0.f));
        Sm1 = add2(Sm1, pk2(inv, 0.f));
        Sm2 = add2(Sm2, pk2(inv * inv, 0.f));
        T2 = add2(T2, pk2(v * lg, 0.f));
        cnt += 1.0f;
    }
}

// Scalar zero-skipping accumulation into a 9-float array.
__device__ __forceinline__ void acc_scalar(float v, float* st) {
    if (v != 0.0f) {
        float inv = rcpa(v), lg = lg2a(v);
        float v2 = v * v, v3 = v2 * v;
        st[0] += v;  st[1] += v2;  st[2] += v3;
        st[3] += v2 * v2;  st[4] += v3 * v2;
        st[5] += inv;  st[6] += inv * inv;
        st[7] += v * lg;  st[8] += 1.0f;
    }
}

__device__ __forceinline__ float wred32(float v) {
#pragma unroll
    for (int o = 16; o; o >>= 1) v += __shfl_down_sync(0xFFFFFFFFu, v, o);
    return v;
}

__global__ void __launch_bounds__(256) fractal_kernel(const float* __restrict__ img,
                                                      const int* __restrict__ bounds,
                                                      float* __restrict__ out) {
    const int b   = blockIdx.x;
    const int tid = threadIdx.x;

    // shared memory (both phases; small)
    __shared__ float  sm18[8][18];     // phase-1 warp partials
    __shared__ double sacc[54];        // phase-2 block stats
    __shared__ float  l3s[512];
    __shared__ float  l4s[64];
    __shared__ float  w2[8][9], w3[8][9], w4[2][9];
    __shared__ float  accF[NBC][6][9];
    __shared__ unsigned int flag;

    // ================= PHASE 1: L0 + L1 stats, write L2 map =================
    {
        const int bc  = b >> 7;
        const int idx = ((b & 127) << 8) | tid;           // 0..32767 (L2 cell in 32^3)
        const int l2w = idx & 31, l2h = (idx >> 5) & 31, l2d = idx >> 10;
        const float* base = img + ((size_t)bc << 21) + (l2d << 16) + (l2h << 9) + (l2w << 2);

        ull S1 = 0, S2 = 0, S3 = 0, S4 = 0, S5 = 0, Sm1 = 0, Sm2 = 0, T2 = 0;
        float cnt0 = 0.0f;
        float st1[9];
#pragma unroll
        for (int j = 0; j < 9; j++) st1[j] = 0.0f;
        float l2v = 0.0f;

#pragma unroll
        for (int cd = 0; cd < 2; cd++)
#pragma unroll
        for (int ch = 0; ch < 2; ch++) {
            const float* q = base + (cd << 15) + (ch << 8);
            ulonglong2 u0 = *reinterpret_cast<const ulonglong2*>(q);           // (sd0,sh0)
            ulonglong2 u1 = *reinterpret_cast<const ulonglong2*>(q + 128);     // (sd0,sh1)
            ulonglong2 u2 = *reinterpret_cast<const ulonglong2*>(q + 16384);   // (sd1,sh0)
            ulonglong2 u3 = *reinterpret_cast<const ulonglong2*>(q + 16512);   // (sd1,sh1)

            ull sum0 = add2(add2(u0.x, u1.x), add2(u2.x, u3.x));
            ull sum1 = add2(add2(u0.y, u1.y), add2(u2.y, u3.y));
            float2 f0 = upk2(sum0), f1 = upk2(sum1);
            float l1a = f0.x + f0.y, l1b = f1.x + f1.y;

            // zero test over all 16 voxels (underflow -> safe exact slow path)
            ull pr = mul2(mul2(mul2(u0.x, u0.y), mul2(u1.x, u1.y)),
                          mul2(mul2(u2.x, u2.y), mul2(u3.x, u3.y)));
            float2 pf = upk2(pr);
            if (pf.x * pf.y != 0.0f) {
                acc_pair(u0.x, S1, S2, S3, S4, S5, Sm1, Sm2, T2);
                acc_pair(u0.y, S1, S2, S3, S4, S5, Sm1, Sm2, T2);
                acc_pair(u1.x, S1, S2, S3, S4, S5, Sm1, Sm2, T2);
                acc_pair(u1.y, S1, S2, S3, S4, S5, Sm1, Sm2, T2);
                acc_pair(u2.x, S1, S2, S3, S4, S5, Sm1, Sm2, T2);
                acc_pair(u2.y, S1, S2, S3, S4, S5, Sm1, Sm2, T2);
                acc_pair(u3.x, S1, S2, S3, S4, S5, Sm1, Sm2, T2);
                acc_pair(u3.y, S1, S2, S3, S4, S5, Sm1, Sm2, T2);
                cnt0 += 16.0f;
            } else {
                float2 a0 = upk2(u0.x), a1 = upk2(u0.y), b0 = upk2(u1.x), b1 = upk2(u1.y);
                float2 c0 = upk2(u2.x), c1 = upk2(u2.y), d0 = upk2(u3.x), d1 = upk2(u3.y);
                float vals[16] = {a0.x, a0.y, a1.x, a1.y, b0.x, b0.y, b1.x, b1.y,
                                  c0.x, c0.y, c1.x, c1.y, d0.x, d0.y, d1.x, d1.y};
#pragma unroll 4
                for (int j = 0; j < 16; j++)
                    acc_one(vals[j], S1, S2, S3, S4, S5, Sm1, Sm2, T2, cnt0);
            }
            acc_scalar(l1a, st1);
            acc_scalar(l1b, st1);
            l2v += l1a + l1b;
        }
        g_l2map[(bc << 15) | idx] = l2v;

        // block reduce 18 stats -> g_part1[b]
        float st0[9];
        {
            float2 f;
            f = upk2(S1);  st0[0] = f.x + f.y;
            f = upk2(S2);  st0[1] = f.x + f.y;
            f = upk2(S3);  st0[2] = f.x + f.y;
            f = upk2(S4);  st0[3] = f.x + f.y;
            f = upk2(S5);  st0[4] = f.x + f.y;
            f = upk2(Sm1); st0[5] = f.x + f.y;
            f = upk2(Sm2); st0[6] = f.x + f.y;
            f = upk2(T2);  st0[7] = f.x + f.y;
            st0[8] = cnt0;
        }
        int lane = tid & 31, warp = tid >> 5;
#pragma unroll
        for (int j = 0; j < 9; j++) {
            float a0 = wred32(st0[j]);
            float a1 = wred32(st1[j]);
            if (lane == 0) { sm18[warp][j] = a0; sm18[warp][9 + j] = a1; }
        }
        __syncthreads();
        if (tid < 18) {
            double s = 0.0;
#pragma unroll
            for (int w = 0; w < 8; w++) s += (double)sm18[w][tid];
            g_part1[b][tid] = s;
        }
        __syncthreads();
        if (tid == 0) { __threadfence(); atomicAdd(&g_ctr1, 1u); }
    }

    if (b >= NB2) return;

    // ================= PHASE 2 (blocks 0..47): L2..L5 =================
    if (tid == 0) {
        while (*(volatile unsigned int*)&g_ctr1 != NB1) __nanosleep(64);
        __threadfence();
    }
    __syncthreads();

    // pre-reduce this block's 16 phase-1 partial rows (18 stats, serial per stat)
    if (tid < 18) {
        double s = 0.0;
#pragma unroll
        for (int r = 0; r < 16; r++) s += g_part1[(b << 4) + r][tid];
        sacc[tid] = s;
    }

    const int bc2 = b >> 3, sub = b & 7;
    const int sw2 = sub & 1, sh2 = (sub >> 1) & 1, sd2 = sub >> 2;
    const int pw = tid & 3, ph = (tid >> 2) & 7, pd = tid >> 5;

    const float* pbase = g_l2map + (bc2 << 15)
                       + (((sd2 << 4) + (pd << 1)) << 10)
                       + (((sh2 << 4) + (ph << 1)) << 5)
                       + (sw2 << 4) + (pw << 2);

    float4 r0 = *reinterpret_cast<const float4*>(pbase);          // (d0,h0)
    float4 r1 = *reinterpret_cast<const float4*>(pbase + 32);     // (d0,h1)
    float4 r2 = *reinterpret_cast<const float4*>(pbase + 1024);   // (d1,h0)
    float4 r3 = *reinterpret_cast<const float4*>(pbase + 1056);   // (d1,h1)

    float st2[9], st3[9];
#pragma unroll
    for (int j = 0; j < 9; j++) { st2[j] = 0.0f; st3[j] = 0.0f; }
    acc_scalar(r0.x, st2); acc_scalar(r0.y, st2); acc_scalar(r0.z, st2); acc_scalar(r0.w, st2);
    acc_scalar(r1.x, st2); acc_scalar(r1.y, st2); acc_scalar(r1.z, st2); acc_scalar(r1.w, st2);
    acc_scalar(r2.x, st2); acc_scalar(r2.y, st2); acc_scalar(r2.z, st2); acc_scalar(r2.w, st2);
    acc_scalar(r3.x, st2); acc_scalar(r3.y, st2); acc_scalar(r3.z, st2); acc_scalar(r3.w, st2);

    float l3a = (r0.x + r0.y) + (r1.x + r1.y) + (r2.x + r2.y) + (r3.x + r3.y);
    float l3b = (r0.z + r0.w) + (r1.z + r1.w) + (r2.z + r2.w) + (r3.z + r3.w);
    acc_scalar(l3a, st3);
    acc_scalar(l3b, st3);
    int l3i = (pd << 6) | (ph << 3) | (pw << 1);
    l3s[l3i] = l3a;
    l3s[l3i + 1] = l3b;
    __syncthreads();

    float st4[9];
#pragma unroll
    for (int j = 0; j < 9; j++) st4[j] = 0.0f;
    if (tid < 64) {
        int jw = tid & 3, jh = (tid >> 2) & 3, jd = tid >> 4;
        int b4 = (jd << 7) | (jh << 4) | (jw << 1);
        float l4v = 0.0f;
#pragma unroll
        for (int di = 0; di < 2; di++)
#pragma unroll
            for (int hi = 0; hi < 2; hi++)
#pragma unroll
                for (int wi = 0; wi < 2; wi++)
                    l4v += l3s[b4 + (di << 6) + (hi << 3) + wi];
        acc_scalar(l4v, st4);
        l4s[tid] = l4v;
    }
    __syncthreads();

    if (tid < 8) {
        int mw = tid & 1, mh = (tid >> 1) & 1, md = tid >> 2;
        int b5 = (md << 5) | (mh << 3) | (mw << 1);
        float l5v = 0.0f;
#pragma unroll
        for (int di = 0; di < 2; di++)
#pragma unroll
            for (int hi = 0; hi < 2; hi++)
#pragma unroll
                for (int wi = 0; wi < 2; wi++)
                    l5v += l4s[b5 + (di << 4) + (hi << 2) + wi];
        float st5[9];
#pragma unroll
        for (int j = 0; j < 9; j++) st5[j] = 0.0f;
        acc_scalar(l5v, st5);
#pragma unroll
        for (int o = 4; o; o >>= 1)
#pragma unroll
            for (int j = 0; j < 9; j++) st5[j] += __shfl_down_sync(0xFFu, st5[j], o);
        if (tid == 0)
#pragma unroll
            for (int j = 0; j < 9; j++) sacc[45 + j] = (double)st5[j];
    }

    // warp staging: st2 AND st3 across all 8 warps; st4 only warps 0,1
    {
        int lane = tid & 31, warp = tid >> 5;
#pragma unroll
        for (int j = 0; j < 9; j++) {
            float a2 = wred32(st2[j]);
            float a3 = wred32(st3[j]);
            if (lane == 0) { w2[warp][j] = a2; w3[warp][j] = a3; }
        }
        if (tid < 64) {
#pragma unroll
            for (int j = 0; j < 9; j++) {
                float a4 = wred32(st4[j]);
                if (lane == 0) w4[warp][j] = a4;
            }
        }
    }
    __syncthreads();

    if (tid < 9) {
        float s = 0.0f;
#pragma unroll
        for (int w = 0; w < 8; w++) s += w2[w][tid];
        sacc[18 + tid] = (double)s;
    } else if (tid >= 16 && tid < 25) {
        int j = tid - 16;
        float s = 0.0f;
#pragma unroll
        for (int w = 0; w < 8; w++) s += w3[w][j];
        sacc[27 + j] = (double)s;
    } else if (tid >= 32 && tid < 41) {
        int j = tid - 32;
        sacc[36 + j] = (double)(w4[0][j] + w4[1][j]);
    }
    __syncthreads();

    if (tid < 54) g_part2[b][tid] = sacc[tid];
    __syncthreads();
    if (tid == 0) {
        __threadfence();
        flag = (atomicAdd(&g_ctr2, 1u) == NB2 - 1) ? 1u : 0u;
    }
    __syncthreads();
    if (!flag) return;
    if (tid == 0) __threadfence();
    __syncthreads();

    // ================= FINALIZE (last phase-2 block) =================
    for (int u = tid; u < NBC * 54; u += 256) {       // 324 items on 256 threads
        int abc = u / 54, j = u % 54;
        double s = 0.0;
#pragma unroll
        for (int t = 0; t < 8; t++) s += g_part2[(abc << 3) + t][j];
        int level, stat;
        if (j < 18) { level = j / 9; stat = j % 9; }
        else        { level = 2 + (j - 18) / 9; stat = (j - 18) % 9; }
        accF[abc][level][stat] = (float)s;
    }
    __syncthreads();

    if (tid == 0) { g_ctr1 = 0; g_ctr2 = 0; }          // reset for next replay

    if (tid >= NBC * 8) return;
    int obc = tid >> 3;
    int k   = bounds[tid & 7];

    const float LN2 = 0.69314718055994531f;
    float bsum = accF[obc][0][0];
    float lnb  = logf(bsum);

    float sp = 0.0f, spq = 0.0f;
    for (int s = 0; s < 6; s++) {
        const float* a = accF[obc][s];
        float pv;
        if (k == 1) {
            pv = (a[7] * LN2) / bsum - lnb;
        } else if (k == 0) {
            pv = logf(a[8]);
        } else {
            float S;
            switch (k) {
                case  2: S = a[1]; break;
                case  3: S = a[2]; break;
                case  4: S = a[3]; break;
                case  5: S = a[4]; break;
                case -1: S = a[5]; break;
                case -2: S = a[6]; break;
                default: S = __int_as_float(0x7FC00000); break;
            }
            pv = logf(S) - (float)k * lnb;
        }
        sp  += pv;
        spq += pv * ((float)s * LN2);
    }
    const float qs  = 15.0f * LN2;
    const float q2s = 55.0f * LN2 * LN2;
    const float den = 6.0f * q2s - qs * qs;
    float aa = (k == 1) ? 1.0f : 1.0f / (float)(k - 1);
    out[tid] = aa * (6.0f * spq - sp * qs) / den;
}

extern "C" void kernel_launch(void* const* d_in, const int* in_sizes, int n_in,
                              void* d_out, int out_size) {
    const float* img    = (const float*)d_in[0];
    const int*   bounds = (const int*)d_in[1];
    float*       out    = (float*)d_out;

    fractal_kernel<<<NB1, 256>>>(img, bounds, out);
}

// round 12
// speedup vs baseline: 1.9655x; 1.2465x over previous
#include <cuda_runtime.h>
#include <math.h>

typedef unsigned long long ull;

#define NBC  6          // B*C
#define NBLK 384        // 64 blocks per bc; block = one 8x8x8 L2-cell region = one L5 cell

// Static __device__ scratch (allocation-free). Zero-init; finalize resets for replay.
__device__ double       g_acc[NBC][54];
__device__ unsigned int g_ctr;

// ---- packed f32x2 helpers (Blackwell 2xFP32; ptxas won't auto-emit) ----
__device__ __forceinline__ ull pk2(float lo, float hi) {
    ull r; asm("mov.b64 %0, {%1, %2};" : "=l"(r) : "f"(lo), "f"(hi)); return r;
}
__device__ __forceinline__ float2 upk2(ull v) {
    float2 f; asm("mov.b64 {%0, %1}, %2;" : "=f"(f.x), "=f"(f.y) : "l"(v)); return f;
}
__device__ __forceinline__ ull add2(ull a, ull b) {
    ull r; asm("add.rn.f32x2 %0, %1, %2;" : "=l"(r) : "l"(a), "l"(b)); return r;
}
__device__ __forceinline__ ull mul2(ull a, ull b) {
    ull r; asm("mul.rn.f32x2 %0, %1, %2;" : "=l"(r) : "l"(a), "l"(b)); return r;
}
__device__ __forceinline__ ull fma2(ull a, ull b, ull c) {
    ull r; asm("fma.rn.f32x2 %0, %1, %2, %3;" : "=l"(r) : "l"(a), "l"(b), "l"(c)); return r;
}
__device__ __forceinline__ float rcpa(float x) {
    float r; asm("rcp.approx.f32 %0, %1;" : "=f"(r) : "f"(x)); return r;
}
__device__ __forceinline__ float lg2a(float x) {
    float r; asm("lg2.approx.f32 %0, %1;" : "=f"(r) : "f"(x)); return r;
}

// Packed pair accumulation, both values nonzero. 3 MUFU (rcp of product trick):
// 1/a + 1/b = (a+b)*rcp(ab);  1/a^2 + 1/b^2 = (a^2+b^2)*rcp(ab)^2.
__device__ __forceinline__ void acc_pair_t(ull x, ull& S1, ull& S2, ull& S3, ull& S4,
                                           ull& S5, float& Sm1, float& Sm2,
                                           float& T2a, float& T2b) {
    float2 f = upk2(x);
    float r  = rcpa(f.x * f.y);             // MUFU.RCP
    float la = lg2a(f.x), lb = lg2a(f.y);   // 2x MUFU.LG2
    S1 = add2(S1, x);
    ull xx = mul2(x, x);
    S2 = add2(S2, xx);
    ull x3 = mul2(xx, x);
    S3 = add2(S3, x3);
    S4 = fma2(xx, xx, S4);
    S5 = fma2(x3, xx, S5);
    float2 fx = upk2(xx);
    Sm1 = fmaf(f.x + f.y, r, Sm1);
    Sm2 = fmaf(fx.x + fx.y, r * r, Sm2);
    T2a = fmaf(f.x, la, T2a);
    T2b = fmaf(f.y, lb, T2b);
}

// Scalar zero-skipping accumulation (rare slow path).
__device__ __forceinline__ void acc_one(float v, ull& S1, ull& S2, ull& S3, ull& S4,
                                        ull& S5, float& Sm1, float& Sm2, float& T2a,
                                        float& cnt) {
    if (v != 0.0f) {
        float inv = rcpa(v), lg = lg2a(v);
        float v2 = v * v, v3 = v2 * v;
        S1 = add2(S1, pk2(v, 0.f));
        S2 = add2(S2, pk2(v2, 0.f));
        S3 = add2(S3, pk2(v3, 0.f));
        S4 = add2(S4, pk2(v2 * v2, 0.f));
        S5 = add2(S5, pk2(v3 * v2, 0.f));
        Sm1 += inv;
        Sm2 += inv * inv;
        T2a = fmaf(v, lg, T2a);
        cnt += 1.0f;
    }
}

// Scalar zero-skipping accumulation into a 9-float stat array.
__device__ __forceinline__ void acc_scalar(float v, float* st) {
    if (v != 0.0f) {
        float inv = rcpa(v), lg = lg2a(v);
        float v2 = v * v, v3 = v2 * v;
        st[0] += v;  st[1] += v2;  st[2] += v3;
        st[3] += v2 * v2;  st[4] += v3 * v2;
        st[5] += inv;  st[6] += inv * inv;
        st[7] += v * lg;  st[8] += 1.0f;
    }
}

__device__ __forceinline__ float wred32(float v) {
#pragma unroll
    for (int o = 16; o; o >>= 1) v += __shfl_down_sync(0xFFFFFFFFu, v, o);
    return v;
}

// One 4^3 cell: L0 stats on 64 voxels, L1 stats on 8 octant sums, L2 stats on cell
// sum. Returns cell sum (the L2 map value).
__device__ __forceinline__ float do_cell(const float* __restrict__ cbase,
                                         ull& S1, ull& S2, ull& S3, ull& S4, ull& S5,
                                         float& Sm1, float& Sm2, float& T2a, float& T2b,
                                         float& cnt, float* st1, float* st2) {
    float l2v = 0.0f;
#pragma unroll
    for (int dzp = 0; dzp < 4; dzp += 2) {
        const float* q = cbase + (dzp << 14);
        // 8 rows of 4 floats (MLP=8 LDG.128): hy 0..3 at dz=dzp, then dz=dzp+1
        ulonglong2 ua = *reinterpret_cast<const ulonglong2*>(q);
        ulonglong2 ub = *reinterpret_cast<const ulonglong2*>(q + 128);
        ulonglong2 uc = *reinterpret_cast<const ulonglong2*>(q + 256);
        ulonglong2 ud = *reinterpret_cast<const ulonglong2*>(q + 384);
        ulonglong2 ue = *reinterpret_cast<const ulonglong2*>(q + 16384);
        ulonglong2 uf = *reinterpret_cast<const ulonglong2*>(q + 16512);
        ulonglong2 ug = *reinterpret_cast<const ulonglong2*>(q + 16640);
        ulonglong2 uh = *reinterpret_cast<const ulonglong2*>(q + 16768);

        // L1 (2x2x2) sums: lo halves = w{0,1}, hi halves = w{2,3}
        ull sl0 = add2(add2(ua.x, ub.x), add2(ue.x, uf.x));   // hy0,1
        ull sl1 = add2(add2(uc.x, ud.x), add2(ug.x, uh.x));   // hy2,3
        ull sh0 = add2(add2(ua.y, ub.y), add2(ue.y, uf.y));
        ull sh1 = add2(add2(uc.y, ud.y), add2(ug.y, uh.y));
        float2 f;
        f = upk2(sl0); float l100 = f.x + f.y;
        f = upk2(sl1); float l101 = f.x + f.y;
        f = upk2(sh0); float l110 = f.x + f.y;
        f = upk2(sh1); float l111 = f.x + f.y;

        // zero test: product of all 32 voxels (underflow -> safe slow path)
        ull p = mul2(mul2(mul2(ua.x, ua.y), mul2(ub.x, ub.y)),
                     mul2(mul2(uc.x, uc.y), mul2(ud.x, ud.y)));
        p = mul2(p, mul2(mul2(ue.x, ue.y), mul2(uf.x, uf.y)));
        p = mul2(p, mul2(mul2(ug.x, ug.y), mul2(uh.x, uh.y)));
        f = upk2(p);
        if (f.x * f.y != 0.0f) {
            acc_pair_t(ua.x, S1, S2, S3, S4, S5, Sm1, Sm2, T2a, T2b);
            acc_pair_t(ua.y, S1, S2, S3, S4, S5, Sm1, Sm2, T2a, T2b);
            acc_pair_t(ub.x, S1, S2, S3, S4, S5, Sm1, Sm2, T2a, T2b);
            acc_pair_t(ub.y, S1, S2, S3, S4, S5, Sm1, Sm2, T2a, T2b);
            acc_pair_t(uc.x, S1, S2, S3, S4, S5, Sm1, Sm2, T2a, T2b);
            acc_pair_t(uc.y, S1, S2, S3, S4, S5, Sm1, Sm2, T2a, T2b);
            acc_pair_t(ud.x, S1, S2, S3, S4, S5, Sm1, Sm2, T2a, T2b);
            acc_pair_t(ud.y, S1, S2, S3, S4, S5, Sm1, Sm2, T2a, T2b);
            acc_pair_t(ue.x, S1, S2, S3, S4, S5, Sm1, Sm2, T2a, T2b);
            acc_pair_t(ue.y, S1, S2, S3, S4, S5, Sm1, Sm2, T2a, T2b);
            acc_pair_t(uf.x, S1, S2, S3, S4, S5, Sm1, Sm2, T2a, T2b);
            acc_pair_t(uf.y, S1, S2, S3, S4, S5, Sm1, Sm2, T2a, T2b);
            acc_pair_t(ug.x, S1, S2, S3, S4, S5, Sm1, Sm2, T2a, T2b);
            acc_pair_t(ug.y, S1, S2, S3, S4, S5, Sm1, Sm2, T2a, T2b);
            acc_pair_t(uh.x, S1, S2, S3, S4, S5, Sm1, Sm2, T2a, T2b);
            acc_pair_t(uh.y, S1, S2, S3, S4, S5, Sm1, Sm2, T2a, T2b);
            cnt += 32.0f;
        } else {
            ull us[16] = {ua.x, ua.y, ub.x, ub.y, uc.x, uc.y, ud.x, ud.y,
                          ue.x, ue.y, uf.x, uf.y, ug.x, ug.y, uh.x, uh.y};
#pragma unroll 4
            for (int j = 0; j < 16; j++) {
                float2 vv = upk2(us[j]);
                acc_one(vv.x, S1, S2, S3, S4, S5, Sm1, Sm2, T2a, cnt);
                acc_one(vv.y, S1, S2, S3, S4, S5, Sm1, Sm2, T2a, cnt);
            }
        }
        acc_scalar(l100, st1);
        acc_scalar(l101, st1);
        acc_scalar(l110, st1);
        acc_scalar(l111, st1);
        l2v += (l100 + l101) + (l110 + l111);
    }
    acc_scalar(l2v, st2);
    return l2v;
}

__global__ void __launch_bounds__(256, 3) fractal_kernel(const float* __restrict__ img,
                                                         const int* __restrict__ bounds,
                                                         float* __restrict__ out) {
    const int b   = blockIdx.x;
    const int tid = threadIdx.x;
    const int bc  = b >> 6, tile = b & 63;
    const int tw = tile & 3, th = (tile >> 2) & 3, td = tile >> 4;
    const int cw = tid & 7, ch = (tid >> 3) & 7, cd0 = tid >> 6;

    __shared__ float l2s[512];
    __shared__ float l3s[64];
    __shared__ float w0[8][9], w1[8][9], w2[8][9], w3[2][9];
    __shared__ float bs[54];
    __shared__ float accF[NBC][54];
    __shared__ unsigned int flag;

    ull S1 = 0, S2 = 0, S3 = 0, S4 = 0, S5 = 0;
    float Sm1 = 0.f, Sm2 = 0.f, T2a = 0.f, T2b = 0.f, cnt = 0.f;
    float st1[9], st2[9];
#pragma unroll
    for (int j = 0; j < 9; j++) { st1[j] = 0.f; st2[j] = 0.f; }

    const float* base0 = img + ((size_t)bc << 21) + (((th << 3) + ch) << 9)
                       + (((tw << 3) + cw) << 2);
    float l2v0 = do_cell(base0 + ((size_t)((td << 3) + cd0) << 16),
                         S1, S2, S3, S4, S5, Sm1, Sm2, T2a, T2b, cnt, st1, st2);
    float l2v1 = do_cell(base0 + ((size_t)((td << 3) + cd0 + 4) << 16),
                         S1, S2, S3, S4, S5, Sm1, Sm2, T2a, T2b, cnt, st1, st2);
    l2s[tid]       = l2v0;   // index (cd<<6)|(ch<<3)|cw == tid for cd0
    l2s[tid + 256] = l2v1;   // cd0+4
    __syncthreads();

    // L3: 64 threads pool 2x2x2 from l2s (8x8x8)
    float st3[9];
    if (tid < 64) {
#pragma unroll
        for (int j = 0; j < 9; j++) st3[j] = 0.f;
        int jw = tid & 3, jh = (tid >> 2) & 3, jd = tid >> 4;
        int b3 = (jd << 7) | (jh << 4) | (jw << 1);
        float l3v = 0.f;
#pragma unroll
        for (int di = 0; di < 2; di++)
#pragma unroll
            for (int hi = 0; hi < 2; hi++)
#pragma unroll
                for (int wi = 0; wi < 2; wi++)
                    l3v += l2s[b3 + (di << 6) + (hi << 3) + wi];
        acc_scalar(l3v, st3);
        l3s[tid] = l3v;
    }
    __syncthreads();

    // L4: 8 threads pool from l3s (4x4x4); L5 = block total by shfl; tid0 -> bs[36..53]
    if (tid < 8) {
        int mw = tid & 1, mh = (tid >> 1) & 1, md = tid >> 2;
        int b4 = (md << 5) | (mh << 3) | (mw << 1);
        float l4v = 0.f;
#pragma unroll
        for (int di = 0; di < 2; di++)
#pragma unroll
            for (int hi = 0; hi < 2; hi++)
#pragma unroll
                for (int wi = 0; wi < 2; wi++)
                    l4v += l3s[b4 + (di << 4) + (hi << 2) + wi];
        float st4[9];
#pragma unroll
        for (int j = 0; j < 9; j++) st4[j] = 0.f;
        acc_scalar(l4v, st4);
        float l5v = l4v;
#pragma unroll
        for (int o = 4; o; o >>= 1) {
            l5v += __shfl_down_sync(0xFFu, l5v, o);
#pragma unroll
            for (int j = 0; j < 9; j++) st4[j] += __shfl_down_sync(0xFFu, st4[j], o);
        }
        if (tid == 0) {
#pragma unroll
            for (int j = 0; j < 9; j++) bs[36 + j] = st4[j];   // L4
            float st5[9];
#pragma unroll
            for (int j = 0; j < 9; j++) st5[j] = 0.f;
            acc_scalar(l5v, st5);
#pragma unroll
            for (int j = 0; j < 9; j++) bs[45 + j] = st5[j];   // L5
        }
    }

    // warp staging: L0/L1/L2 across 8 warps, L3 across warps 0,1
    {
        float st0[9];
        float2 f;
        f = upk2(S1); st0[0] = f.x + f.y;
        f = upk2(S2); st0[1] = f.x + f.y;
        f = upk2(S3); st0[2] = f.x + f.y;
        f = upk2(S4); st0[3] = f.x + f.y;
        f = upk2(S5); st0[4] = f.x + f.y;
        st0[5] = Sm1; st0[6] = Sm2; st0[7] = T2a + T2b; st0[8] = cnt;
        int lane = tid & 31, warp = tid >> 5;
#pragma unroll
        for (int j = 0; j < 9; j++) {
            float a0 = wred32(st0[j]);
            float a1 = wred32(st1[j]);
            float a2 = wred32(st2[j]);
            if (lane == 0) { w0[warp][j] = a0; w1[warp][j] = a1; w2[warp][j] = a2; }
        }
        if (tid < 64) {
#pragma unroll
            for (int j = 0; j < 9; j++) {
                float a3 = wred32(st3[j]);
                if (lane == 0) w3[warp][j] = a3;
            }
        }
    }
    __syncthreads();

    if (tid < 9) {
        float s = 0.f;
#pragma unroll
        for (int w = 0; w < 8; w++) s += w0[w][tid];
        bs[tid] = s;
    } else if (tid >= 32 && tid < 41) {
        int j = tid - 32;
        float s = 0.f;
#pragma unroll
        for (int w = 0; w < 8; w++) s += w1[w][j];
        bs[9 + j] = s;
    } else if (tid >= 64 && tid < 73) {
        int j = tid - 64;
        float s = 0.f;
#pragma unroll
        for (int w = 0; w < 8; w++) s += w2[w][j];
        bs[18 + j] = s;
    } else if (tid >= 96 && tid < 105) {
        int j = tid - 96;
        bs[27 + j] = w3[0][j] + w3[1][j];
    }
    __syncthreads();

    // global accumulate (RED.ADD.F64, 54 spread addresses) + arrival
    if (tid < 54) {
        atomicAdd(&g_acc[bc][tid], (double)bs[tid]);
        __threadfence();
    }
    __syncthreads();
    if (tid == 0) flag = (atomicAdd(&g_ctr, 1u) == NBLK - 1) ? 1u : 0u;
    __syncthreads();
    if (!flag) return;
    if (tid == 0) __threadfence();
    __syncthreads();

    // ================= FINALIZE (last block) =================
    for (int u = tid; u < NBC * 54; u += 256)
        accF[u / 54][u % 54] = (float)g_acc[u / 54][u % 54];
    __syncthreads();
    // reset for next graph replay
    for (int u = tid; u < NBC * 54; u += 256) g_acc[u / 54][u % 54] = 0.0;
    if (tid == 0) g_ctr = 0;

    if (tid >= NBC * 8) return;
    int obc = tid >> 3;
    int k   = bounds[tid & 7];

    const float LN2 = 0.69314718055994531f;
    float bsum = accF[obc][0];              // L0 S1 = total image sum
    float lnb  = logf(bsum);

    float sp = 0.0f, spq = 0.0f;
    for (int s = 0; s < 6; s++) {
        const float* a = &accF[obc][s * 9];
        float pv;
        if (k == 1) {
            pv = (a[7] * LN2) / bsum - lnb;
        } else if (k == 0) {
            pv = logf(a[8]);
        } else {
            float S;
            switch (k) {
                case  2: S = a[1]; break;
                case  3: S = a[2]; break;
                case  4: S = a[3]; break;
                case  5: S = a[4]; break;
                case -1: S = a[5]; break;
                case -2: S = a[6]; break;
                default: S = __int_as_float(0x7FC00000); break;
            }
            pv = logf(S) - (float)k * lnb;
        }
        sp  += pv;
        spq += pv * ((float)s * LN2);
    }
    const float qs  = 15.0f * LN2;
    const float q2s = 55.0f * LN2 * LN2;
    const float den = 6.0f * q2s - qs * qs;
    float aa = (k == 1) ? 1.0f : 1.0f / (float)(k - 1);
    out[tid] = aa * (6.0f * spq - sp * qs) / den;
}

extern "C" void kernel_launch(void* const* d_in, const int* in_sizes, int n_in,
                              void* d_out, int out_size) {
    const float* img    = (const float*)d_in[0];
    const int*   bounds = (const int*)d_in[1];
    float*       out    = (float*)d_out;

    fractal_kernel<<<NBLK, 256>>>(img, bounds, out);
}